// round 3
// baseline (speedup 1.0000x reference)
#include <cuda_runtime.h>
#include <math.h>

#define SEQT 512
#define NB   256
#define OBS  128
#define LAT  64
#define HID  256
#define MB   (SEQT*NB)

// ------------------------- device scratch ----------------------------------
__device__ float g_h1  [(size_t)MB*HID];
__device__ float g_phix[(size_t)MB*HID];
__device__ float g_encx[(size_t)MB*HID];
__device__ float g_gxx [(size_t)MB*3*HID];
__device__ float g_h   [2][NB*HID];
__device__ float g_A   [NB*HID];
__device__ float g_E   [NB*HID];
__device__ float g_GH  [NB*3*HID];
__device__ float g_D1h [NB*HID];
__device__ float g_D   [NB*HID];
__device__ float g_post[NB*2*LAT];
__device__ float g_phiz[NB*HID];
__device__ float g_gxz [NB*3*HID];

__device__ unsigned          g_bar_cnt;
__device__ volatile unsigned g_bar_gen;

// ------------------------- grid barrier ------------------------------------
__device__ __forceinline__ void grid_sync()
{
    __syncthreads();
    if (threadIdx.x == 0) {
        __threadfence();
        unsigned my = g_bar_gen;
        if (atomicAdd(&g_bar_cnt, 1u) == gridDim.x - 1u) {
            g_bar_cnt = 0u;
            __threadfence();
            g_bar_gen = my + 1u;
        } else {
            while (g_bar_gen == my) { __nanosleep(40); }
        }
        __threadfence();
    }
    __syncthreads();
}

// ------------------------- 64x64 GEMM tile ---------------------------------
// C = epi( [addend +] A[row0.. , :K] @ W[col0.. , :K]^T [+ bias] )
// A row-major [*,lda], W row-major [*,ldw]. 256 threads, 4x4 per thread.
// aMode 0: load A.  aMode 2: z on the fly from (zpost, zeps), K must be 64.
// epMode 0: store C[row*ldc+col].
// epMode 1: col<64 -> C[row*64+col], col>=64 -> out2[row*64+col-64];
//           if postbuf, also postbuf[row*128+col].
__device__ __noinline__ void do_tile(
    int aMode, const float* __restrict__ A, int lda,
    const float* __restrict__ W, int ldw, int K, int row0, int col0,
    const float* __restrict__ zpost, const float* __restrict__ zeps,
    int epMode, const float* __restrict__ bias,
    const float* __restrict__ addend, int ldadd, int doRelu,
    float* __restrict__ C, int ldc,
    float* __restrict__ out2, float* __restrict__ postbuf)
{
    __shared__ float sA[64*68];
    __shared__ float sW[64*68];
    const int tid = threadIdx.x;
    const int r   = tid & 63;
    const int q   = tid >> 6;
    const int r0  = (tid >> 4) << 2;
    const int c0  = (tid & 15) << 2;

    float acc[16];
#pragma unroll
    for (int i = 0; i < 16; i++) acc[i] = 0.f;

    for (int k0 = 0; k0 < K; k0 += 64) {
#pragma unroll
        for (int j = 0; j < 4; j++) {
            int kk = q + j * 4;
            int k  = k0 + kk * 4;
            float4 v;
            if (aMode == 0) {
                v = *(const float4*)(A + (size_t)(row0 + r) * lda + k);
            } else {
                int rg = row0 + r;
                float4 pm = *(const float4*)(zpost + rg * 128 + k);
                float4 pl = *(const float4*)(zpost + rg * 128 + 64 + k);
                float4 ev = *(const float4*)(zeps  + rg * 64 + k);
                v.x = pm.x + ev.x * expf(0.5f * pl.x);
                v.y = pm.y + ev.y * expf(0.5f * pl.y);
                v.z = pm.z + ev.z * expf(0.5f * pl.z);
                v.w = pm.w + ev.w * expf(0.5f * pl.w);
            }
            float* d = sA + (kk * 4) * 68 + r;
            d[0] = v.x; d[68] = v.y; d[136] = v.z; d[204] = v.w;

            float4 wv = *(const float4*)(W + (size_t)(col0 + r) * ldw + k);
            float* dw = sW + (kk * 4) * 68 + r;
            dw[0] = wv.x; dw[68] = wv.y; dw[136] = wv.z; dw[204] = wv.w;
        }
        __syncthreads();
#pragma unroll 8
        for (int kk = 0; kk < 64; kk++) {
            float4 a = *(const float4*)(sA + kk * 68 + r0);
            float4 w = *(const float4*)(sW + kk * 68 + c0);
            acc[0]  += a.x*w.x; acc[1]  += a.x*w.y; acc[2]  += a.x*w.z; acc[3]  += a.x*w.w;
            acc[4]  += a.y*w.x; acc[5]  += a.y*w.y; acc[6]  += a.y*w.z; acc[7]  += a.y*w.w;
            acc[8]  += a.z*w.x; acc[9]  += a.z*w.y; acc[10] += a.z*w.z; acc[11] += a.z*w.w;
            acc[12] += a.w*w.x; acc[13] += a.w*w.y; acc[14] += a.w*w.z; acc[15] += a.w*w.w;
        }
        __syncthreads();
    }

#pragma unroll
    for (int i = 0; i < 4; i++) {
        int row = row0 + r0 + i;
#pragma unroll
        for (int j = 0; j < 4; j++) {
            int col = col0 + c0 + j;
            float v = acc[i * 4 + j];
            if (bias)   v += bias[col];
            if (addend) v += addend[(size_t)row * ldadd + col];
            if (doRelu) v = fmaxf(v, 0.f);
            if (epMode == 0) {
                C[(size_t)row * ldc + col] = v;
            } else {
                if (postbuf) postbuf[row * 128 + col] = v;
                if (col < 64) C[row * 64 + col] = v;
                else          out2[row * 64 + (col - 64)] = v;
            }
        }
    }
}

// ------------------------- phase-1 GEMM kernel ------------------------------
extern "C" __global__ void __launch_bounds__(256)
gemm_nt(const float* __restrict__ A, int lda,
        const float* __restrict__ W, int ldw,
        const float* __restrict__ bias,
        float* __restrict__ C, int ldc, int K, int doRelu)
{
    do_tile(0, A, lda, W, ldw, K, blockIdx.y * 64, blockIdx.x * 64,
            0, 0, 0, bias, 0, 0, doRelu, C, ldc, 0, 0);
}

// ------------------------- persistent recurrent kernel ----------------------
extern "C" __global__ void __launch_bounds__(256)
vrnn_loop(const float* __restrict__ eps,
          const float* __restrict__ prior_w1, const float* __restrict__ prior_b1,
          const float* __restrict__ prior_w2, const float* __restrict__ prior_b2,
          const float* __restrict__ enc_w1,
          const float* __restrict__ enc_w2,  const float* __restrict__ enc_b2,
          const float* __restrict__ phi_z_w, const float* __restrict__ phi_z_b,
          const float* __restrict__ dec_w1,  const float* __restrict__ dec_b1,
          const float* __restrict__ dec_w2,  const float* __restrict__ dec_b2,
          const float* __restrict__ gru_wih, const float* __restrict__ gru_whh,
          const float* __restrict__ gru_bhh,
          float* __restrict__ out)
{
    float* out_rec  = out;
    float* out_prm  = out + (size_t)SEQT * NB * OBS;
    float* out_prlv = out_prm  + (size_t)SEQT * NB * LAT;
    float* out_pom  = out_prlv + (size_t)SEQT * NB * LAT;
    float* out_polv = out_pom  + (size_t)SEQT * NB * LAT;

    for (int i = blockIdx.x * 256 + threadIdx.x; i < NB * HID; i += gridDim.x * 256)
        g_h[0][i] = 0.f;
    grid_sync();

    for (int t = 0; t < SEQT; t++) {
        const float* h    = g_h[t & 1];
        float*       hnew = g_h[(t + 1) & 1];

        // Stage 1: all h-only GEMMs + deferred decoder output of step t-1
        int n1 = (t > 0) ? 104 : 96;
        for (int u = blockIdx.x; u < n1; u += gridDim.x) {
            if (u < 16) {
                do_tile(0, h, HID, prior_w1, HID, HID, (u>>2)*64, (u&3)*64, 0, 0,
                        0, prior_b1, 0, 0, 1, g_A, HID, 0, 0);
            } else if (u < 32) {
                int v = u - 16;
                do_tile(0, h, HID, enc_w1 + HID, 2*HID, HID, (v>>2)*64, (v&3)*64, 0, 0,
                        0, 0, g_encx + (size_t)t*NB*HID, HID, 1, g_E, HID, 0, 0);
            } else if (u < 80) {
                int v = u - 32;
                do_tile(0, h, HID, gru_whh, HID, HID, (v/12)*64, (v%12)*64, 0, 0,
                        0, gru_bhh, 0, 0, 0, g_GH, 3*HID, 0, 0);
            } else if (u < 96) {
                int v = u - 80;
                do_tile(0, h, HID, dec_w1 + HID, 2*HID, HID, (v>>2)*64, (v&3)*64, 0, 0,
                        0, 0, 0, 0, 0, g_D1h, HID, 0, 0);
            } else {
                int v = u - 96;
                do_tile(0, g_D, HID, dec_w2, HID, HID, (v>>1)*64, (v&1)*64, 0, 0,
                        0, dec_b2, 0, 0, 0,
                        out_rec + (size_t)(t-1)*NB*OBS, OBS, 0, 0);
            }
        }
        grid_sync();

        // Stage 2: prior L2 + posterior L2 (latent splits)
        for (int u = blockIdx.x; u < 16; u += gridDim.x) {
            if (u < 8) {
                do_tile(0, g_A, HID, prior_w2, HID, HID, (u>>1)*64, (u&1)*64, 0, 0,
                        1, prior_b2, 0, 0, 0,
                        out_prm + (size_t)t*NB*LAT, 0,
                        out_prlv + (size_t)t*NB*LAT, 0);
            } else {
                int v = u - 8;
                do_tile(0, g_E, HID, enc_w2, HID, HID, (v>>1)*64, (v&1)*64, 0, 0,
                        1, enc_b2, 0, 0, 0,
                        out_pom + (size_t)t*NB*LAT, 0,
                        out_polv + (size_t)t*NB*LAT, g_post);
            }
        }
        grid_sync();

        // Stage 3: phi_z = relu(z @ phi_z_w^T + b), z generated inline
        for (int u = blockIdx.x; u < 16; u += gridDim.x) {
            do_tile(2, 0, 0, phi_z_w, LAT, LAT, (u>>2)*64, (u&3)*64,
                    g_post, eps + (size_t)t*NB*LAT,
                    0, phi_z_b, 0, 0, 1, g_phiz, HID, 0, 0);
        }
        grid_sync();

        // Stage 4: decoder L1 (phi_z half, + D1h) and gxz
        for (int u = blockIdx.x; u < 64; u += gridDim.x) {
            if (u < 16) {
                do_tile(0, g_phiz, HID, dec_w1, 2*HID, HID, (u>>2)*64, (u&3)*64, 0, 0,
                        0, dec_b1, g_D1h, HID, 1, g_D, HID, 0, 0);
            } else {
                int v = u - 16;
                do_tile(0, g_phiz, HID, gru_wih + HID, 2*HID, HID, (v/12)*64, (v%12)*64,
                        0, 0, 0, 0, 0, 0, 0, g_gxz, 3*HID, 0, 0);
            }
        }
        grid_sync();

        // Stage 5: GRU gates
        {
            const float* gxx = g_gxx + (size_t)t * NB * 3 * HID;
            for (int i = blockIdx.x * 256 + threadIdx.x; i < NB * HID;
                 i += gridDim.x * 256) {
                int b = i >> 8, c = i & 255;
                const float* gx = gxx   + b * 768;
                const float* gz = g_gxz + b * 768;
                const float* gh = g_GH  + b * 768;
                float xr = gx[c]     + gz[c];
                float xz = gx[256+c] + gz[256+c];
                float xn = gx[512+c] + gz[512+c];
                float rg = 1.f / (1.f + expf(-(xr + gh[c])));
                float zg = 1.f / (1.f + expf(-(xz + gh[256+c])));
                float nn = tanhf(xn + rg * gh[512+c]);
                hnew[i] = (1.f - zg) * nn + zg * h[i];
            }
        }
        grid_sync();
    }

    // deferred decoder output for the last step
    for (int u = blockIdx.x; u < 8; u += gridDim.x) {
        do_tile(0, g_D, HID, dec_w2, HID, HID, (u>>1)*64, (u&1)*64, 0, 0,
                0, dec_b2, 0, 0, 0,
                out_rec + (size_t)(SEQT-1)*NB*OBS, OBS, 0, 0);
    }
}

// ------------------------- host launcher ------------------------------------
extern "C" void kernel_launch(void* const* d_in, const int* in_sizes, int n_in,
                              void* d_out, int out_size)
{
    const float* x        = (const float*)d_in[0];
    const float* eps      = (const float*)d_in[1];
    const float* phi_x_w1 = (const float*)d_in[2];
    const float* phi_x_b1 = (const float*)d_in[3];
    const float* phi_x_w2 = (const float*)d_in[4];
    const float* phi_x_b2 = (const float*)d_in[5];
    const float* phi_z_w  = (const float*)d_in[6];
    const float* phi_z_b  = (const float*)d_in[7];
    const float* prior_w1 = (const float*)d_in[8];
    const float* prior_b1 = (const float*)d_in[9];
    const float* prior_w2 = (const float*)d_in[10];
    const float* prior_b2 = (const float*)d_in[11];
    const float* enc_w1   = (const float*)d_in[12];
    const float* enc_b1   = (const float*)d_in[13];
    const float* enc_w2   = (const float*)d_in[14];
    const float* enc_b2   = (const float*)d_in[15];
    const float* dec_w1   = (const float*)d_in[16];
    const float* dec_b1   = (const float*)d_in[17];
    const float* dec_w2   = (const float*)d_in[18];
    const float* dec_b2   = (const float*)d_in[19];
    const float* gru_wih  = (const float*)d_in[20];
    const float* gru_whh  = (const float*)d_in[21];
    const float* gru_bih  = (const float*)d_in[22];
    const float* gru_bhh  = (const float*)d_in[23];

    float *p_h1, *p_phix, *p_encx, *p_gxx;
    cudaGetSymbolAddress((void**)&p_h1,   g_h1);
    cudaGetSymbolAddress((void**)&p_phix, g_phix);
    cudaGetSymbolAddress((void**)&p_encx, g_encx);
    cudaGetSymbolAddress((void**)&p_gxx,  g_gxx);

    int nsm = 148;
    cudaDeviceGetAttribute(&nsm, cudaDevAttrMultiProcessorCount, 0);
    // Clamp persistent grid to guaranteed-co-resident CTA count (barrier safety).
    int maxPerSm = 1;
    cudaOccupancyMaxActiveBlocksPerMultiprocessor(&maxPerSm, vrnn_loop, 256, 0);
    if (maxPerSm < 1) maxPerSm = 1;
    int grid = nsm * maxPerSm;
    if (grid > nsm) grid = nsm;          // 1 CTA/SM is all we want

    dim3 blk(256);
    // Phase 1: parallel GEMMs over all SEQ*B rows (2048 row tiles)
    gemm_nt<<<dim3(4, 2048),  blk>>>(x,      OBS,  phi_x_w1, OBS,   phi_x_b1, p_h1,   HID,   OBS, 1);
    gemm_nt<<<dim3(4, 2048),  blk>>>(p_h1,   HID,  phi_x_w2, HID,   phi_x_b2, p_phix, HID,   HID, 0);
    gemm_nt<<<dim3(4, 2048),  blk>>>(p_phix, HID,  enc_w1,   2*HID, enc_b1,   p_encx, HID,   HID, 0);
    gemm_nt<<<dim3(12, 2048), blk>>>(p_phix, HID,  gru_wih,  2*HID, gru_bih,  p_gxx,  3*HID, HID, 0);

    // Phase 2: persistent recurrent kernel
    vrnn_loop<<<grid, blk>>>(eps, prior_w1, prior_b1, prior_w2, prior_b2,
                             enc_w1, enc_w2, enc_b2, phi_z_w, phi_z_b,
                             dec_w1, dec_b1, dec_w2, dec_b2,
                             gru_wih, gru_whh, gru_bhh, (float*)d_out);
}

// round 4
// speedup vs baseline: 1.3510x; 1.3510x over previous
#include <cuda_runtime.h>
#include <math.h>

#define SEQT 512
#define NB   256
#define OBS  128
#define LAT  64
#define HID  256
#define MB   (SEQT*NB)

// ------------------------- device scratch ----------------------------------
__device__ float g_h1   [(size_t)MB*HID];
__device__ float g_phix [(size_t)MB*HID];
__device__ float g_encx [(size_t)MB*HID];           // includes enc_b1
__device__ float g_gxx  [(size_t)MB*3*HID];         // includes gru_bih
__device__ float g_h    [2][NB*HID];
__device__ float g_Ep   [4][NB*HID];                // h@enc_w1h partials
__device__ float g_Ap   [4][NB*HID];                // h@prior_w1 partials
__device__ float g_GHp  [4][NB*3*HID];              // h@gru_whh partials
__device__ float g_D1hp [2][4][NB*HID];             // h@dec_w1h partials (parity)
__device__ float g_postp[4][NB*2*LAT];              // E@enc_w2 partials
__device__ float g_priorp[4][NB*2*LAT];             // A@prior_w2 partials
__device__ float g_phiz [NB*HID];                   // full, post-relu
__device__ float g_gxzp [4][NB*3*HID];              // phiz@gru_wih_z partials
__device__ float g_Dp   [4][NB*HID];                // phiz@dec_w1x partials
__device__ float g_recp [4][NB*OBS];                // D@dec_w2 partials

__device__ unsigned          g_bar_cnt;
__device__ volatile unsigned g_bar_gen;

#define PSTR_H   ((size_t)NB*HID)
#define PSTR_L   ((size_t)NB*2*LAT)
#define PSTR_G   ((size_t)NB*3*HID)
#define PSTR_R   ((size_t)NB*OBS)

// ------------------------- grid barrier ------------------------------------
__device__ __forceinline__ void grid_sync()
{
    __syncthreads();
    if (threadIdx.x == 0) {
        __threadfence();
        unsigned my = g_bar_gen;
        if (atomicAdd(&g_bar_cnt, 1u) == gridDim.x - 1u) {
            g_bar_cnt = 0u;
            __threadfence();
            g_bar_gen = my + 1u;
        } else {
            while (g_bar_gen == my) { __nanosleep(20); }
        }
        __threadfence();
    }
    __syncthreads();
}

// ------------------------- 64x64x64 GEMM chunk ------------------------------
// C_chunk[row0..+64, col0..+64] = Aop[rows, kA0..kA0+64] @ W[col0..+64, kW0..+64]^T
// aSel 0 (PLAIN):  Aop = A[row*lda + kA0 + k]
// aSel 1 (SUM4R):  Aop = relu( sum_{c<4} A[c*pstr + row*lda+kA0+k]
//                            [+ sum_{c<4} B2[c*pstr + ...]] [+ add[row*lda+kA0+k]]
//                            [+ abias[kA0+k]] )
// aSel 2 (ZGEN):   Aop = pm + eps*exp(0.5*pl), pm/pl = sum4(postp)+abias; lda=128
// Epilogue: v (+cbias[col]) (relu if crelu) -> C[row*ldc+col]
__device__ __noinline__ void tile_chunk(
    int aSel,
    const float* __restrict__ A, int lda, int kA0,
    const float* __restrict__ B2, size_t pstr,
    const float* __restrict__ add, const float* __restrict__ abias,
    const float* __restrict__ epsT,
    const float* __restrict__ W, int ldw, int kW0,
    int row0, int col0,
    float* __restrict__ C, int ldc,
    const float* __restrict__ cbias, int crelu)
{
    __shared__ float sA[64*68];
    __shared__ float sW[64*68];
    const int tid = threadIdx.x;
    const int r   = tid & 63;
    const int q   = tid >> 6;
    const int r0  = (tid >> 4) << 2;
    const int c0  = (tid & 15) << 2;

    float acc[16];
#pragma unroll
    for (int i = 0; i < 16; i++) acc[i] = 0.f;

#pragma unroll
    for (int j = 0; j < 4; j++) {
        int kk = q + j * 4;
        int k  = kk * 4;
        float4 v;
        if (aSel == 0) {
            v = *(const float4*)(A + (size_t)(row0 + r) * lda + kA0 + k);
        } else if (aSel == 1) {
            const float* p = A + (size_t)(row0 + r) * lda + kA0 + k;
            float4 s0 = *(const float4*)(p);
            float4 s1 = *(const float4*)(p + pstr);
            float4 s2 = *(const float4*)(p + 2 * pstr);
            float4 s3 = *(const float4*)(p + 3 * pstr);
            v.x = s0.x + s1.x + s2.x + s3.x;
            v.y = s0.y + s1.y + s2.y + s3.y;
            v.z = s0.z + s1.z + s2.z + s3.z;
            v.w = s0.w + s1.w + s2.w + s3.w;
            if (B2) {
                const float* p2 = B2 + (size_t)(row0 + r) * lda + kA0 + k;
                float4 t0 = *(const float4*)(p2);
                float4 t1 = *(const float4*)(p2 + pstr);
                float4 t2 = *(const float4*)(p2 + 2 * pstr);
                float4 t3 = *(const float4*)(p2 + 3 * pstr);
                v.x += t0.x + t1.x + t2.x + t3.x;
                v.y += t0.y + t1.y + t2.y + t3.y;
                v.z += t0.z + t1.z + t2.z + t3.z;
                v.w += t0.w + t1.w + t2.w + t3.w;
            }
            if (add) {
                float4 a4 = *(const float4*)(add + (size_t)(row0 + r) * lda + kA0 + k);
                v.x += a4.x; v.y += a4.y; v.z += a4.z; v.w += a4.w;
            }
            if (abias) {
                float4 b4 = *(const float4*)(abias + kA0 + k);
                v.x += b4.x; v.y += b4.y; v.z += b4.z; v.w += b4.w;
            }
            v.x = fmaxf(v.x, 0.f); v.y = fmaxf(v.y, 0.f);
            v.z = fmaxf(v.z, 0.f); v.w = fmaxf(v.w, 0.f);
        } else {
            int rg = row0 + r;
            const float* pm0 = A + (size_t)rg * 128 + k;
            const float* pl0 = A + (size_t)rg * 128 + 64 + k;
            float4 m0 = *(const float4*)(pm0);
            float4 m1 = *(const float4*)(pm0 + pstr);
            float4 m2 = *(const float4*)(pm0 + 2 * pstr);
            float4 m3 = *(const float4*)(pm0 + 3 * pstr);
            float4 l0 = *(const float4*)(pl0);
            float4 l1 = *(const float4*)(pl0 + pstr);
            float4 l2 = *(const float4*)(pl0 + 2 * pstr);
            float4 l3 = *(const float4*)(pl0 + 3 * pstr);
            float4 bm = *(const float4*)(abias + k);
            float4 bl = *(const float4*)(abias + 64 + k);
            float4 ev = *(const float4*)(epsT + (size_t)rg * 64 + k);
            float pmx = m0.x + m1.x + m2.x + m3.x + bm.x;
            float pmy = m0.y + m1.y + m2.y + m3.y + bm.y;
            float pmz = m0.z + m1.z + m2.z + m3.z + bm.z;
            float pmw = m0.w + m1.w + m2.w + m3.w + bm.w;
            float plx = l0.x + l1.x + l2.x + l3.x + bl.x;
            float ply = l0.y + l1.y + l2.y + l3.y + bl.y;
            float plz = l0.z + l1.z + l2.z + l3.z + bl.z;
            float plw = l0.w + l1.w + l2.w + l3.w + bl.w;
            v.x = pmx + ev.x * expf(0.5f * plx);
            v.y = pmy + ev.y * expf(0.5f * ply);
            v.z = pmz + ev.z * expf(0.5f * plz);
            v.w = pmw + ev.w * expf(0.5f * plw);
        }
        float* d = sA + k * 68 + r;
        d[0] = v.x; d[68] = v.y; d[136] = v.z; d[204] = v.w;

        float4 wv = *(const float4*)(W + (size_t)(col0 + r) * ldw + kW0 + k);
        float* dw = sW + k * 68 + r;
        dw[0] = wv.x; dw[68] = wv.y; dw[136] = wv.z; dw[204] = wv.w;
    }
    __syncthreads();
#pragma unroll 8
    for (int kk = 0; kk < 64; kk++) {
        float4 a = *(const float4*)(sA + kk * 68 + r0);
        float4 w = *(const float4*)(sW + kk * 68 + c0);
        acc[0]  += a.x*w.x; acc[1]  += a.x*w.y; acc[2]  += a.x*w.z; acc[3]  += a.x*w.w;
        acc[4]  += a.y*w.x; acc[5]  += a.y*w.y; acc[6]  += a.y*w.z; acc[7]  += a.y*w.w;
        acc[8]  += a.z*w.x; acc[9]  += a.z*w.y; acc[10] += a.z*w.z; acc[11] += a.z*w.w;
        acc[12] += a.w*w.x; acc[13] += a.w*w.y; acc[14] += a.w*w.z; acc[15] += a.w*w.w;
    }
    __syncthreads();

#pragma unroll
    for (int i = 0; i < 4; i++) {
        int row = row0 + r0 + i;
#pragma unroll
        for (int j = 0; j < 4; j++) {
            int col = col0 + c0 + j;
            float v = acc[i * 4 + j];
            if (cbias) v += cbias[col];
            if (crelu) v = fmaxf(v, 0.f);
            C[(size_t)row * ldc + col] = v;
        }
    }
}

// ------------------------- reduce helpers -----------------------------------
// partials [4][NB*128] + bias[128] -> split halves into two [NB*64] outputs
__device__ __forceinline__ void red_latent(int unit, const float (*P)[NB*2*LAT],
                                           const float* __restrict__ bias,
                                           float* __restrict__ om, float* __restrict__ olv)
{
    // 32768 elems / 4 units = 8192 = 2048 float4/unit
    for (int e4 = unit * 2048 + threadIdx.x; e4 < (unit + 1) * 2048; e4 += 256) {
        int idx = e4 * 4, row = idx >> 7, col = idx & 127;
        float4 s0 = *(const float4*)(&P[0][idx]);
        float4 s1 = *(const float4*)(&P[1][idx]);
        float4 s2 = *(const float4*)(&P[2][idx]);
        float4 s3 = *(const float4*)(&P[3][idx]);
        float4 b  = *(const float4*)(bias + col);
        float4 v;
        v.x = s0.x+s1.x+s2.x+s3.x+b.x; v.y = s0.y+s1.y+s2.y+s3.y+b.y;
        v.z = s0.z+s1.z+s2.z+s3.z+b.z; v.w = s0.w+s1.w+s2.w+s3.w+b.w;
        if (col < 64) *(float4*)(om  + row * 64 + col)      = v;
        else          *(float4*)(olv + row * 64 + col - 64) = v;
    }
}

__device__ __forceinline__ void red_rec(int unit, const float (*P)[NB*OBS],
                                        const float* __restrict__ bias,
                                        float* __restrict__ out)
{
    // 32768 elems / 8 units = 4096 = 1024 float4/unit
    for (int e4 = unit * 1024 + threadIdx.x; e4 < (unit + 1) * 1024; e4 += 256) {
        int idx = e4 * 4, col = idx & 127;
        float4 s0 = *(const float4*)(&P[0][idx]);
        float4 s1 = *(const float4*)(&P[1][idx]);
        float4 s2 = *(const float4*)(&P[2][idx]);
        float4 s3 = *(const float4*)(&P[3][idx]);
        float4 b  = *(const float4*)(bias + col);
        float4 v;
        v.x = s0.x+s1.x+s2.x+s3.x+b.x; v.y = s0.y+s1.y+s2.y+s3.y+b.y;
        v.z = s0.z+s1.z+s2.z+s3.z+b.z; v.w = s0.w+s1.w+s2.w+s3.w+b.w;
        *(float4*)(out + idx) = v;
    }
}

// ------------------------- phase-1 GEMM kernel ------------------------------
extern "C" __global__ void __launch_bounds__(256)
gemm_nt(const float* __restrict__ A, int lda,
        const float* __restrict__ W, int ldw,
        const float* __restrict__ bias,
        float* __restrict__ C, int ldc, int K, int doRelu)
{
    __shared__ float sA[64*68];
    __shared__ float sW[64*68];
    const int tid = threadIdx.x;
    const int r   = tid & 63;
    const int q   = tid >> 6;
    const int r0  = (tid >> 4) << 2;
    const int c0  = (tid & 15) << 2;
    int row0 = blockIdx.y * 64, col0 = blockIdx.x * 64;

    float acc[16];
#pragma unroll
    for (int i = 0; i < 16; i++) acc[i] = 0.f;

    for (int k0 = 0; k0 < K; k0 += 64) {
#pragma unroll
        for (int j = 0; j < 4; j++) {
            int kk = q + j * 4, k = kk * 4;
            float4 v  = *(const float4*)(A + (size_t)(row0 + r) * lda + k0 + k);
            float* d = sA + k * 68 + r;
            d[0] = v.x; d[68] = v.y; d[136] = v.z; d[204] = v.w;
            float4 wv = *(const float4*)(W + (size_t)(col0 + r) * ldw + k0 + k);
            float* dw = sW + k * 68 + r;
            dw[0] = wv.x; dw[68] = wv.y; dw[136] = wv.z; dw[204] = wv.w;
        }
        __syncthreads();
#pragma unroll 8
        for (int kk = 0; kk < 64; kk++) {
            float4 a = *(const float4*)(sA + kk * 68 + r0);
            float4 w = *(const float4*)(sW + kk * 68 + c0);
            acc[0]  += a.x*w.x; acc[1]  += a.x*w.y; acc[2]  += a.x*w.z; acc[3]  += a.x*w.w;
            acc[4]  += a.y*w.x; acc[5]  += a.y*w.y; acc[6]  += a.y*w.z; acc[7]  += a.y*w.w;
            acc[8]  += a.z*w.x; acc[9]  += a.z*w.y; acc[10] += a.z*w.z; acc[11] += a.z*w.w;
            acc[12] += a.w*w.x; acc[13] += a.w*w.y; acc[14] += a.w*w.z; acc[15] += a.w*w.w;
        }
        __syncthreads();
    }
#pragma unroll
    for (int i = 0; i < 4; i++) {
        int row = row0 + r0 + i;
#pragma unroll
        for (int j = 0; j < 4; j++) {
            int col = col0 + c0 + j;
            float v = acc[i * 4 + j] + bias[col];
            if (doRelu) v = fmaxf(v, 0.f);
            C[(size_t)row * ldc + col] = v;
        }
    }
}

// ------------------------- persistent recurrent kernel ----------------------
extern "C" __global__ void __launch_bounds__(256)
vrnn_loop(const float* __restrict__ eps,
          const float* __restrict__ prior_w1, const float* __restrict__ prior_b1,
          const float* __restrict__ prior_w2, const float* __restrict__ prior_b2,
          const float* __restrict__ enc_w1,
          const float* __restrict__ enc_w2,  const float* __restrict__ enc_b2,
          const float* __restrict__ phi_z_w, const float* __restrict__ phi_z_b,
          const float* __restrict__ dec_w1,  const float* __restrict__ dec_b1,
          const float* __restrict__ dec_w2,  const float* __restrict__ dec_b2,
          const float* __restrict__ gru_wih, const float* __restrict__ gru_whh,
          const float* __restrict__ gru_bhh,
          float* __restrict__ out)
{
    float* out_rec  = out;
    float* out_prm  = out + (size_t)SEQT * NB * OBS;
    float* out_prlv = out_prm  + (size_t)SEQT * NB * LAT;
    float* out_pom  = out_prlv + (size_t)SEQT * NB * LAT;
    float* out_polv = out_pom  + (size_t)SEQT * NB * LAT;
    const int bid = blockIdx.x, grid = gridDim.x;

    for (int i = bid * 256 + threadIdx.x; i < NB * HID; i += grid * 256)
        g_h[0][i] = 0.f;
    grid_sync();

    for (int t = 0; t < SEQT; t++) {
        const float* h    = g_h[t & 1];
        float*       hnew = g_h[(t + 1) & 1];
        const float* epsT = eps + (size_t)t * NB * LAT;
        float (*D1hc)[NB*HID] = g_D1hp[t & 1];         // this step's D1h partials
        float (*D1hp)[NB*HID] = g_D1hp[(t ^ 1) & 1];   // previous step's

        // ---- Stage 1: E(64) | A(64) | redPrior(t-1)(4) | decout(t-1) u0..15 ----
        {
            int cnt = (t > 0) ? 148 : 128;
            for (int u = bid; u < cnt; u += grid) {
                if (u < 64) {
                    int i = u >> 2, c = u & 3;
                    tile_chunk(0, h, HID, c*64, 0, 0, 0, 0, 0,
                               enc_w1 + HID, 2*HID, c*64, (i>>2)*64, (i&3)*64,
                               g_Ep[c], HID, 0, 0);
                } else if (u < 128) {
                    int w = u - 64, i = w >> 2, c = w & 3;
                    tile_chunk(0, h, HID, c*64, 0, 0, 0, 0, 0,
                               prior_w1, HID, c*64, (i>>2)*64, (i&3)*64,
                               g_Ap[c], HID, 0, 0);
                } else if (u < 132) {
                    red_latent(u - 128, g_priorp, prior_b2,
                               out_prm + (size_t)(t-1)*NB*LAT,
                               out_prlv + (size_t)(t-1)*NB*LAT);
                } else {
                    int w = u - 132, i = w >> 2, c = w & 3;   // decout units 0..15
                    tile_chunk(1, g_Dp[0], HID, c*64, D1hp[0], PSTR_H, 0, dec_b1, 0,
                               dec_w2, HID, c*64, (i>>1)*64, (i&1)*64,
                               g_recp[c], OBS, 0, 0);
                }
            }
        }
        grid_sync();

        // ---- Stage 2: post(32) | priorOut(32) | GH chunks 0..83 ----
        for (int u = bid; u < 148; u += grid) {
            if (u < 32) {
                int i = u >> 2, c = u & 3;
                tile_chunk(1, g_Ep[0], HID, c*64, 0, PSTR_H,
                           g_encx + (size_t)t*NB*HID, 0, 0,
                           enc_w2, HID, c*64, (i>>1)*64, (i&1)*64,
                           g_postp[c], 128, 0, 0);
            } else if (u < 64) {
                int w = u - 32, i = w >> 2, c = w & 3;
                tile_chunk(1, g_Ap[0], HID, c*64, 0, PSTR_H, 0, prior_b1, 0,
                           prior_w2, HID, c*64, (i>>1)*64, (i&1)*64,
                           g_priorp[c], 128, 0, 0);
            } else {
                int v = u - 64, i = v >> 2, c = v & 3;       // GH units 0..83
                tile_chunk(0, h, HID, c*64, 0, 0, 0, 0, 0,
                           gru_whh, HID, c*64, (i/12)*64, (i%12)*64,
                           g_GHp[c], 3*HID, 0, 0);
            }
        }
        grid_sync();

        // ---- Stage 3: phiz(16) | redPost(4) | D1h u0..3 | decout(t-1) u16..31 | GH 84..191 ----
        for (int u = bid; u < 148; u += grid) {
            if (u < 16) {
                int i = u;
                tile_chunk(2, g_postp[0], 128, 0, 0, PSTR_L, 0, enc_b2, epsT,
                           phi_z_w, LAT, 0, (i>>2)*64, (i&3)*64,
                           g_phiz, HID, phi_z_b, 1);
            } else if (u < 20) {
                red_latent(u - 16, g_postp, enc_b2,
                           out_pom + (size_t)t*NB*LAT,
                           out_polv + (size_t)t*NB*LAT);
            } else if (u < 24) {
                int v = u - 20, i = v >> 2, c = v & 3;       // D1h units 0..3
                tile_chunk(0, h, HID, c*64, 0, 0, 0, 0, 0,
                           dec_w1 + HID, 2*HID, c*64, (i>>2)*64, (i&3)*64,
                           D1hc[c], HID, 0, 0);
            } else if (u < 40) {
                if (t > 0) {
                    int w = u - 24 + 16, i = w >> 2, c = w & 3;  // decout units 16..31
                    tile_chunk(1, g_Dp[0], HID, c*64, D1hp[0], PSTR_H, 0, dec_b1, 0,
                               dec_w2, HID, c*64, (i>>1)*64, (i&1)*64,
                               g_recp[c], OBS, 0, 0);
                }
            } else {
                int v = u - 40 + 84, i = v >> 2, c = v & 3;  // GH units 84..191
                tile_chunk(0, h, HID, c*64, 0, 0, 0, 0, 0,
                           gru_whh, HID, c*64, (i/12)*64, (i%12)*64,
                           g_GHp[c], 3*HID, 0, 0);
            }
        }
        grid_sync();

        // ---- Stage 4: gxz units 0..147 ----
        for (int u = bid; u < 148; u += grid) {
            int i = u >> 2, c = u & 3;
            tile_chunk(0, g_phiz, HID, c*64, 0, 0, 0, 0, 0,
                       gru_wih + HID, 2*HID, c*64, (i/12)*64, (i%12)*64,
                       g_gxzp[c], 3*HID, 0, 0);
        }
        grid_sync();

        // ---- Stage 5: gxz 148..191 (44) | decL1(64) | D1h u4..43 (40) ----
        for (int u = bid; u < 148; u += grid) {
            if (u < 44) {
                int v = u + 148, i = v >> 2, c = v & 3;
                tile_chunk(0, g_phiz, HID, c*64, 0, 0, 0, 0, 0,
                           gru_wih + HID, 2*HID, c*64, (i/12)*64, (i%12)*64,
                           g_gxzp[c], 3*HID, 0, 0);
            } else if (u < 108) {
                int w = u - 44, i = w >> 2, c = w & 3;
                tile_chunk(0, g_phiz, HID, c*64, 0, 0, 0, 0, 0,
                           dec_w1, 2*HID, c*64, (i>>2)*64, (i&3)*64,
                           g_Dp[c], HID, 0, 0);
            } else {
                int v = u - 108 + 4, i = v >> 2, c = v & 3;  // D1h units 4..43
                tile_chunk(0, h, HID, c*64, 0, 0, 0, 0, 0,
                           dec_w1 + HID, 2*HID, c*64, (i>>2)*64, (i&3)*64,
                           D1hc[c], HID, 0, 0);
            }
        }
        grid_sync();

        // ---- Stage 6: gates(64) | D1h u44..63 (20) | redRec(t-1)(8) ----
        {
            const float* gxx = g_gxx + (size_t)t * NB * 3 * HID;
            int cnt = (t > 0) ? 92 : 84;
            for (int u = bid; u < cnt; u += grid) {
                if (u < 64) {
                    int e4 = u * 256 + threadIdx.x;           // one float4 per thread
                    int idx = e4 * 4, b = idx >> 8, cc = idx & 255;
                    const float* gx = gxx + b * 768;
                    float4 xr = *(const float4*)(gx + cc);
                    float4 xz = *(const float4*)(gx + 256 + cc);
                    float4 xn = *(const float4*)(gx + 512 + cc);
                    float4 hr = *(const float4*)(gru_bhh + cc);
                    float4 hz = *(const float4*)(gru_bhh + 256 + cc);
                    float4 hn = *(const float4*)(gru_bhh + 512 + cc);
#pragma unroll
                    for (int c = 0; c < 4; c++) {
                        const float* gz = &g_gxzp[c][b * 768];
                        float4 a0 = *(const float4*)(gz + cc);
                        float4 a1 = *(const float4*)(gz + 256 + cc);
                        float4 a2 = *(const float4*)(gz + 512 + cc);
                        xr.x += a0.x; xr.y += a0.y; xr.z += a0.z; xr.w += a0.w;
                        xz.x += a1.x; xz.y += a1.y; xz.z += a1.z; xz.w += a1.w;
                        xn.x += a2.x; xn.y += a2.y; xn.z += a2.z; xn.w += a2.w;
                        const float* gh = &g_GHp[c][b * 768];
                        float4 b0 = *(const float4*)(gh + cc);
                        float4 b1 = *(const float4*)(gh + 256 + cc);
                        float4 b2 = *(const float4*)(gh + 512 + cc);
                        hr.x += b0.x; hr.y += b0.y; hr.z += b0.z; hr.w += b0.w;
                        hz.x += b1.x; hz.y += b1.y; hz.z += b1.z; hz.w += b1.w;
                        hn.x += b2.x; hn.y += b2.y; hn.z += b2.z; hn.w += b2.w;
                    }
                    float4 hold = *(const float4*)(h + idx);
                    float4 o;
                    {
                        float rg = 1.f/(1.f+expf(-(xr.x+hr.x)));
                        float zg = 1.f/(1.f+expf(-(xz.x+hz.x)));
                        float nn = tanhf(xn.x + rg*hn.x);
                        o.x = (1.f-zg)*nn + zg*hold.x;
                        rg = 1.f/(1.f+expf(-(xr.y+hr.y)));
                        zg = 1.f/(1.f+expf(-(xz.y+hz.y)));
                        nn = tanhf(xn.y + rg*hn.y);
                        o.y = (1.f-zg)*nn + zg*hold.y;
                        rg = 1.f/(1.f+expf(-(xr.z+hr.z)));
                        zg = 1.f/(1.f+expf(-(xz.z+hz.z)));
                        nn = tanhf(xn.z + rg*hn.z);
                        o.z = (1.f-zg)*nn + zg*hold.z;
                        rg = 1.f/(1.f+expf(-(xr.w+hr.w)));
                        zg = 1.f/(1.f+expf(-(xz.w+hz.w)));
                        nn = tanhf(xn.w + rg*hn.w);
                        o.w = (1.f-zg)*nn + zg*hold.w;
                    }
                    *(float4*)(hnew + idx) = o;
                } else if (u < 84) {
                    int v = u - 64 + 44, i = v >> 2, c = v & 3;  // D1h units 44..63
                    tile_chunk(0, h, HID, c*64, 0, 0, 0, 0, 0,
                               dec_w1 + HID, 2*HID, c*64, (i>>2)*64, (i&3)*64,
                               D1hc[c], HID, 0, 0);
                } else {
                    red_rec(u - 84, g_recp, dec_b2,
                            out_rec + (size_t)(t-1)*NB*OBS);
                }
            }
        }
        grid_sync();
    }

    // ---- Tail 1: decout(511) all 32 units + redPrior(511) ----
    for (int u = bid; u < 36; u += grid) {
        if (u < 32) {
            int i = u >> 2, c = u & 3;
            tile_chunk(1, g_Dp[0], HID, c*64, g_D1hp[(SEQT-1)&1][0], PSTR_H, 0, dec_b1, 0,
                       dec_w2, HID, c*64, (i>>1)*64, (i&1)*64,
                       g_recp[c], OBS, 0, 0);
        } else {
            red_latent(u - 32, g_priorp, prior_b2,
                       out_prm + (size_t)(SEQT-1)*NB*LAT,
                       out_prlv + (size_t)(SEQT-1)*NB*LAT);
        }
    }
    grid_sync();
    // ---- Tail 2: redRec(511) ----
    for (int u = bid; u < 8; u += grid)
        red_rec(u, g_recp, dec_b2, out_rec + (size_t)(SEQT-1)*NB*OBS);
}

// ------------------------- host launcher ------------------------------------
extern "C" void kernel_launch(void* const* d_in, const int* in_sizes, int n_in,
                              void* d_out, int out_size)
{
    const float* x        = (const float*)d_in[0];
    const float* eps      = (const float*)d_in[1];
    const float* phi_x_w1 = (const float*)d_in[2];
    const float* phi_x_b1 = (const float*)d_in[3];
    const float* phi_x_w2 = (const float*)d_in[4];
    const float* phi_x_b2 = (const float*)d_in[5];
    const float* phi_z_w  = (const float*)d_in[6];
    const float* phi_z_b  = (const float*)d_in[7];
    const float* prior_w1 = (const float*)d_in[8];
    const float* prior_b1 = (const float*)d_in[9];
    const float* prior_w2 = (const float*)d_in[10];
    const float* prior_b2 = (const float*)d_in[11];
    const float* enc_w1   = (const float*)d_in[12];
    const float* enc_b1   = (const float*)d_in[13];
    const float* enc_w2   = (const float*)d_in[14];
    const float* enc_b2   = (const float*)d_in[15];
    const float* dec_w1   = (const float*)d_in[16];
    const float* dec_b1   = (const float*)d_in[17];
    const float* dec_w2   = (const float*)d_in[18];
    const float* dec_b2   = (const float*)d_in[19];
    const float* gru_wih  = (const float*)d_in[20];
    const float* gru_whh  = (const float*)d_in[21];
    const float* gru_bih  = (const float*)d_in[22];
    const float* gru_bhh  = (const float*)d_in[23];

    float *p_h1, *p_phix, *p_encx, *p_gxx;
    cudaGetSymbolAddress((void**)&p_h1,   g_h1);
    cudaGetSymbolAddress((void**)&p_phix, g_phix);
    cudaGetSymbolAddress((void**)&p_encx, g_encx);
    cudaGetSymbolAddress((void**)&p_gxx,  g_gxx);

    int nsm = 148;
    cudaDeviceGetAttribute(&nsm, cudaDevAttrMultiProcessorCount, 0);
    int maxPerSm = 1;
    cudaOccupancyMaxActiveBlocksPerMultiprocessor(&maxPerSm, vrnn_loop, 256, 0);
    if (maxPerSm < 1) maxPerSm = 1;
    int grid = nsm;   // 1 CTA/SM; maxPerSm>=1 guaranteed resident

    dim3 blk(256);
    // Phase 1: parallel GEMMs over all SEQ*B rows
    gemm_nt<<<dim3(4, 2048),  blk>>>(x,      OBS,  phi_x_w1, OBS,   phi_x_b1, p_h1,   HID,   OBS, 1);
    gemm_nt<<<dim3(4, 2048),  blk>>>(p_h1,   HID,  phi_x_w2, HID,   phi_x_b2, p_phix, HID,   HID, 0);
    gemm_nt<<<dim3(4, 2048),  blk>>>(p_phix, HID,  enc_w1,   2*HID, enc_b1,   p_encx, HID,   HID, 0);
    gemm_nt<<<dim3(12, 2048), blk>>>(p_phix, HID,  gru_wih,  2*HID, gru_bih,  p_gxx,  3*HID, HID, 0);

    // Phase 2: persistent recurrent kernel
    vrnn_loop<<<grid, blk>>>(eps, prior_w1, prior_b1, prior_w2, prior_b2,
                             enc_w1, enc_w2, enc_b2, phi_z_w, phi_z_b,
                             dec_w1, dec_b1, dec_w2, dec_b2,
                             gru_wih, gru_whh, gru_bhh, (float*)d_out);
}